// round 4
// baseline (speedup 1.0000x reference)
#include <cuda_runtime.h>
#include <math.h>

#define IMG    64
#define NSLICE 16
#define NCOIL  4
#define NSING  4
#define NECHO  3
#define NRO    32
#define NPT    96
#define NEC    (NECHO * NCOIL)   // 12
#define NPIX   (IMG * IMG)       // 4096

typedef unsigned long long u64;

// ---- packed f32x2 helpers ---------------------------------------------------
__device__ __forceinline__ u64 pack2(float lo, float hi) {
    u64 r;
    asm("mov.b64 %0, {%1, %2};" : "=l"(r)
        : "r"(__float_as_uint(lo)), "r"(__float_as_uint(hi)));
    return r;
}
__device__ __forceinline__ u64 dup2(float v) { return pack2(v, v); }
__device__ __forceinline__ void fma2(u64& d, u64 a, u64 b) {
    asm("fma.rn.f32x2 %0, %1, %2, %3;" : "=l"(d) : "l"(a), "l"(b), "l"(d));
}
__device__ __forceinline__ float2 unpack2(u64 v) {
    unsigned lo, hi;
    asm("mov.b64 {%0, %1}, %2;" : "=r"(lo), "=r"(hi) : "l"(v));
    return make_float2(__uint_as_float(lo), __uint_as_float(hi));
}

// scf[kz][c][j=n*3+e][pix]  (25 MB)
__device__ float2 g_scf[NSLICE * NCOIL * (NSING * NECHO) * NPIX];
// imgW[r][ec=e*4+c][pix]    (12.6 MB)
__device__ float2 g_imgW[NRO * NEC * NPIX];
// phase tables [r][x][p]
__device__ float2 g_exp_[NRO * IMG * NPT];   // exp(-i*w0*(x-32))          = (re, im)
__device__ float2 g_exr_[NRO * IMG * NPT];   // rotated:                    (-im, re)
__device__ float2 g_ey_[NRO * IMG * NPT];    // exp(-i*w1*(y-32))

// ---------------------------------------------------------------------------
// Stage A: z-DFT (all 16 kz) of sign(z)*singulars*smap, per (pix, c, n).
// Scalar FFMA version (round-2). grid (16 pixblocks, 16 = c*4+n), block 256.
// ---------------------------------------------------------------------------
__global__ __launch_bounds__(256, 2)
void stageA_kernel(const float* __restrict__ singulars,   // [64,64,16,4,3,2]
                   const float* __restrict__ smap)        // [4,64,64,16,2]
{
    const int pix = blockIdx.x * 256 + threadIdx.x;
    const int cn  = blockIdx.y;
    const int c   = cn >> 2;
    const int n   = cn & 3;
    const int x   = pix & (IMG - 1);
    const int y   = pix >> 6;

    __shared__ float2 W[NSLICE][NSLICE];
    {
        int kz = threadIdx.x >> 4, z = threadIdx.x & 15;
        float ang = -(2.0f * (float)M_PI / (float)NSLICE) * (float)(kz * z);
        float s, co; sincosf(ang, &s, &co);
        float sgn = (z & 1) ? -1.0f : 1.0f;
        W[kz][z] = make_float2(co * sgn, s * sgn);
    }
    __syncthreads();

    const float* vbase = singulars + ((size_t)(x * IMG + y) * NSLICE) * (NSING * NECHO * 2) + n * 6;
    const float* sbase = smap + ((size_t)(c * NPIX + x * IMG + y) * NSLICE) * 2;

    float accr[NSLICE][NECHO];
    float acci[NSLICE][NECHO];
#pragma unroll
    for (int kz = 0; kz < NSLICE; ++kz)
#pragma unroll
        for (int e = 0; e < NECHO; ++e) { accr[kz][e] = 0.f; acci[kz][e] = 0.f; }

    for (int z = 0; z < NSLICE; ++z) {
        float2 sm = *(const float2*)(sbase + z * 2);
        const float* v = vbase + z * (NSING * NECHO * 2);
        float2 v0 = *(const float2*)(v + 0);
        float2 v1 = *(const float2*)(v + 2);
        float2 v2 = *(const float2*)(v + 4);

        float tr[3], ti[3];
        tr[0] = v0.x * sm.x - v0.y * sm.y;  ti[0] = v0.x * sm.y + v0.y * sm.x;
        tr[1] = v1.x * sm.x - v1.y * sm.y;  ti[1] = v1.x * sm.y + v1.y * sm.x;
        tr[2] = v2.x * sm.x - v2.y * sm.y;  ti[2] = v2.x * sm.y + v2.y * sm.x;

#pragma unroll
        for (int kz = 0; kz < NSLICE; ++kz) {
            float2 w = W[kz][z];
#pragma unroll
            for (int e = 0; e < NECHO; ++e) {
                accr[kz][e] = fmaf(tr[e], w.x, accr[kz][e]);
                accr[kz][e] = fmaf(-ti[e], w.y, accr[kz][e]);
                acci[kz][e] = fmaf(tr[e], w.y, acci[kz][e]);
                acci[kz][e] = fmaf(ti[e], w.x, acci[kz][e]);
            }
        }
    }

#pragma unroll
    for (int kz = 0; kz < NSLICE; ++kz)
#pragma unroll
        for (int e = 0; e < NECHO; ++e) {
            g_scf[((size_t)(kz * NCOIL + c) * (NSING * NECHO) + n * NECHO + e) * NPIX + pix]
                = make_float2(accr[kz][e], acci[kz][e]);
        }
}

// ---------------------------------------------------------------------------
// Stage B: mix with Ur, gather slice bin: imgW[r][e*4+c][pix]
// ---------------------------------------------------------------------------
__global__ __launch_bounds__(256)
void stageB_kernel(const float* __restrict__ ur_list,   // [1,32,4]
                   const int*   __restrict__ sbin)      // [32]
{
    const int pix = blockIdx.x * 256 + threadIdx.x;
    const int r   = blockIdx.y;
    const int kzr = sbin[r];

    float u[NSING];
#pragma unroll
    for (int n = 0; n < NSING; ++n) u[n] = ur_list[r * NSING + n];

    const float2* base = g_scf + (size_t)(kzr * NCOIL) * (NSING * NECHO) * NPIX;

#pragma unroll
    for (int e = 0; e < NECHO; ++e) {
#pragma unroll
        for (int c = 0; c < NCOIL; ++c) {
            float ar = 0.f, ai = 0.f;
#pragma unroll
            for (int n = 0; n < NSING; ++n) {
                float2 s = base[((size_t)c * (NSING * NECHO) + n * NECHO + e) * NPIX + pix];
                ar = fmaf(u[n], s.x, ar);
                ai = fmaf(u[n], s.y, ai);
            }
            g_imgW[((size_t)r * NEC + e * NCOIL + c) * NPIX + pix] = make_float2(ar, ai);
        }
    }
}

// ---------------------------------------------------------------------------
// Phase tables, parallel over 4 x-segments of 16. grid 32, block 384.
// Writes ex, rotated ex, ey.
// ---------------------------------------------------------------------------
__global__ __launch_bounds__(384)
void exgen_kernel(const float* __restrict__ ktraj)   // [1,32,96,2]
{
    const int r = blockIdx.x;
    const int p = threadIdx.x % NPT;
    const int g = threadIdx.x / NPT;       // 0..3, 16 steps each
    const float w0 = ktraj[(r * NPT + p) * 2 + 0];
    const float w1 = ktraj[(r * NPT + p) * 2 + 1];

    {
        float s, c; sincosf(w0, &s, &c);                     // step exp(-i*w0)
        float pr, pi; sincosf(w0 * (32.0f - g * 16.0f), &pi, &pr);
#pragma unroll 4
        for (int j = 0; j < 16; ++j) {
            int x = g * 16 + j;
            size_t idx = ((size_t)r * IMG + x) * NPT + p;
            g_exp_[idx] = make_float2(pr, pi);
            g_exr_[idx] = make_float2(-pi, pr);
            float t = pr;
            pr = fmaf(pr, c, pi * s);
            pi = fmaf(pi, c, -(t * s));
        }
    }
    {
        float s, c; sincosf(w1, &s, &c);
        float pr, pi; sincosf(w1 * (32.0f - g * 16.0f), &pi, &pr);
#pragma unroll 4
        for (int j = 0; j < 16; ++j) {
            int y = g * 16 + j;
            g_ey_[((size_t)r * IMG + y) * NPT + p] = make_float2(pr, pi);
            float t = pr;
            pr = fmaf(pr, c, pi * s);
            pi = fmaf(pi, c, -(t * s));
        }
    }
}

// ---------------------------------------------------------------------------
// NUFFT: block = (r, group of 3 ec), 384 threads, single wave (128 blocks).
// ex slabs (plain + rotated, all 64 x) resident for all 3 images.
// Image double-buffered; thread tile 4p x 4y with strided p mapping
// {2tx, 2tx+1, 2tx+48, 2tx+49} -> conflict-free 16B shared loads.
// ---------------------------------------------------------------------------
#define TS2   66   // padded y-stride (float2) for transposed image

__global__ __launch_bounds__(384)
void nufft_kernel(float2* __restrict__ out)   // [96,4,32,3] complex
{
    extern __shared__ unsigned char shraw[];
    float2* sT   = (float2*)shraw;                              // [2][64][TS2]
    float2* sEp  = (float2*)(shraw + 2 * IMG * TS2 * sizeof(float2));   // [64][96]
    float2* sEr  = sEp + IMG * NPT;                             // [64][96]
    float2* sRed = sEr + IMG * NPT;                             // [96][16]

    const int r   = blockIdx.x;
    const int ecg = blockIdx.y;          // 0..3 -> ec = 3*ecg + k
    const int tid = threadIdx.x;
    const int tx  = tid % 24;
    const int ty  = tid / 24;
    const int y0  = ty * 4;
    const int ec0 = ecg * 3;

    // load ex tables (resident across all 3 images)
    {
        const float2* gp = g_exp_ + (size_t)r * IMG * NPT;
        const float2* gr = g_exr_ + (size_t)r * IMG * NPT;
        for (int i = tid; i < IMG * NPT; i += 384) {
            sEp[i] = gp[i];
            sEr[i] = gr[i];
        }
    }
    // first image, transposed: sT[x][y]
    {
        const float2* gi = g_imgW + ((size_t)r * NEC + ec0) * NPIX;
        for (int i = tid; i < NPIX; i += 384) {
            int x = i & 63, y = i >> 6;
            sT[x * TS2 + y] = gi[i];
        }
    }
    __syncthreads();

    const float2* gey = g_ey_ + (size_t)r * IMG * NPT;

    for (int k = 0; k < 3; ++k) {
        const float2* sTk = sT + (k & 1) * IMG * TS2;

        u64 acc[4][4];
#pragma unroll
        for (int a = 0; a < 4; ++a)
#pragma unroll
            for (int b = 0; b < 4; ++b) acc[a][b] = 0ull;

#pragma unroll 2
        for (int xl = 0; xl < IMG; ++xl) {
            const u64* pe = (const u64*)(sEp + xl * NPT);
            const u64* pr = (const u64*)(sEr + xl * NPT);
            ulonglong2 epA = *(const ulonglong2*)(pe + 2 * tx);       // p, p+1
            ulonglong2 epB = *(const ulonglong2*)(pe + 2 * tx + 48);  // p+48, p+49
            ulonglong2 erA = *(const ulonglong2*)(pr + 2 * tx);
            ulonglong2 erB = *(const ulonglong2*)(pr + 2 * tx + 48);

            const float4* ti = (const float4*)(sTk + xl * TS2 + y0);
            float4 i01 = ti[0], i23 = ti[1];
            float ivx[4] = { i01.x, i01.z, i23.x, i23.z };
            float ivy[4] = { i01.y, i01.w, i23.y, i23.w };

#pragma unroll
            for (int yy = 0; yy < 4; ++yy) {
                u64 dx = dup2(ivx[yy]);
                u64 dy = dup2(ivy[yy]);
                fma2(acc[0][yy], dx, epA.x); fma2(acc[0][yy], dy, erA.x);
                fma2(acc[1][yy], dx, epA.y); fma2(acc[1][yy], dy, erA.y);
                fma2(acc[2][yy], dx, epB.x); fma2(acc[2][yy], dy, erB.x);
                fma2(acc[3][yy], dx, epB.y); fma2(acc[3][yy], dy, erB.y);
            }
        }

        // prefetch next image into the other buffer (safe: that buffer's last
        // readers all passed the previous iteration's barriers)
        if (k < 2) {
            const float2* gn = g_imgW + ((size_t)r * NEC + ec0 + k + 1) * NPIX;
            float2* sTn = sT + ((k + 1) & 1) * IMG * TS2;
            for (int i = tid; i < NPIX; i += 384) {
                int x = i & 63, y = i >> 6;
                sTn[x * TS2 + y] = gn[i];
            }
        }

        // epilogue: contract with ey, reduce over ty groups
        const int pg[4] = { 2 * tx, 2 * tx + 1, 2 * tx + 48, 2 * tx + 49 };
#pragma unroll
        for (int pp = 0; pp < 4; ++pp) {
            float orr = 0.f, oii = 0.f;
#pragma unroll
            for (int yy = 0; yy < 4; ++yy) {
                float2 t  = unpack2(acc[pp][yy]);
                float2 ey = gey[(y0 + yy) * NPT + pg[pp]];
                orr = fmaf(t.x,  ey.x, orr);
                orr = fmaf(-t.y, ey.y, orr);
                oii = fmaf(t.x,  ey.y, oii);
                oii = fmaf(t.y,  ey.x, oii);
            }
            sRed[pg[pp] * 16 + ty] = make_float2(orr, oii);
        }
        __syncthreads();

        if (tid < NPT) {
            float sr = 0.f, si = 0.f;
#pragma unroll
            for (int q = 0; q < 16; ++q) {
                float2 v = sRed[tid * 16 + q];
                sr += v.x; si += v.y;
            }
            const int ec = ec0 + k;
            const int e  = ec >> 2;
            const int c  = ec & 3;
            out[((tid * NCOIL + c) * NRO + r) * NECHO + e] = make_float2(sr, si);
        }
        __syncthreads();
    }
}

// ---------------------------------------------------------------------------
extern "C" void kernel_launch(void* const* d_in, const int* in_sizes, int n_in,
                              void* d_out, int out_size)
{
    const float* singulars = (const float*)d_in[0];
    const float* smap      = (const float*)d_in[1];
    const float* ktraj     = (const float*)d_in[2];
    const float* ur_list   = (const float*)d_in[3];
    const int*   sbin      = (const int*)d_in[4];
    // d_in[5] = dc (unused by the forward reference)

    float2* out = (float2*)d_out;

    const int smemNufft = (2 * IMG * TS2 + 2 * IMG * NPT + NPT * 16) * (int)sizeof(float2);
    cudaFuncSetAttribute(nufft_kernel, cudaFuncAttributeMaxDynamicSharedMemorySize, smemNufft);

    stageA_kernel<<<dim3(NPIX / 256, 16), 256>>>(singulars, smap);
    exgen_kernel<<<NRO, 384>>>(ktraj);
    stageB_kernel<<<dim3(NPIX / 256, NRO), 256>>>(ur_list, sbin);
    nufft_kernel<<<dim3(NRO, 4), 384, smemNufft>>>(out);
}

// round 5
// speedup vs baseline: 1.0262x; 1.0262x over previous
#include <cuda_runtime.h>
#include <math.h>

#define IMG    64
#define NSLICE 16
#define NCOIL  4
#define NSING  4
#define NECHO  3
#define NRO    32
#define NPT    96
#define NEC    (NECHO * NCOIL)   // 12
#define NPIX   (IMG * IMG)       // 4096

typedef unsigned long long u64;

// ---- packed f32x2 helpers ---------------------------------------------------
__device__ __forceinline__ u64 pack2(float lo, float hi) {
    u64 r;
    asm("mov.b64 %0, {%1, %2};" : "=l"(r)
        : "r"(__float_as_uint(lo)), "r"(__float_as_uint(hi)));
    return r;
}
__device__ __forceinline__ u64 dup2(float v) { return pack2(v, v); }
__device__ __forceinline__ void fma2(u64& d, u64 a, u64 b) {
    asm("fma.rn.f32x2 %0, %1, %2, %3;" : "=l"(d) : "l"(a), "l"(b), "l"(d));
}
__device__ __forceinline__ float2 unpack2(u64 v) {
    unsigned lo, hi;
    asm("mov.b64 {%0, %1}, %2;" : "=r"(lo), "=r"(hi) : "l"(v));
    return make_float2(__uint_as_float(lo), __uint_as_float(hi));
}

// scf[kz][c][j=n*3+e][pix]  (25 MB)
__device__ float2 g_scf[NSLICE * NCOIL * (NSING * NECHO) * NPIX];
// imgW[r][ec=e*4+c][pix]    (12.6 MB)
__device__ float2 g_imgW[NRO * NEC * NPIX];
// phase tables [r][x][p]
__device__ float2 g_exp_[NRO * IMG * NPT];   // exp(-i*w0*(x-32)) = (re, im)
__device__ float2 g_exr_[NRO * IMG * NPT];   // rotated:            (-im, re)
__device__ float2 g_ey_[NRO * IMG * NPT];    // exp(-i*w1*(y-32))

// ---------------------------------------------------------------------------
// Stage A: z-DFT (all 16 kz) of sign(z)*singulars*smap, per (pix, c, n).
// Scalar FFMA (best measured). grid (16 pixblocks, 16 = c*4+n), block 256.
// ---------------------------------------------------------------------------
__global__ __launch_bounds__(256, 2)
void stageA_kernel(const float* __restrict__ singulars,   // [64,64,16,4,3,2]
                   const float* __restrict__ smap)        // [4,64,64,16,2]
{
    const int pix = blockIdx.x * 256 + threadIdx.x;
    const int cn  = blockIdx.y;
    const int c   = cn >> 2;
    const int n   = cn & 3;
    const int x   = pix & (IMG - 1);
    const int y   = pix >> 6;

    __shared__ float2 W[NSLICE][NSLICE];
    {
        int kz = threadIdx.x >> 4, z = threadIdx.x & 15;
        float ang = -(2.0f * (float)M_PI / (float)NSLICE) * (float)(kz * z);
        float s, co; sincosf(ang, &s, &co);
        float sgn = (z & 1) ? -1.0f : 1.0f;
        W[kz][z] = make_float2(co * sgn, s * sgn);
    }
    __syncthreads();

    const float* vbase = singulars + ((size_t)(x * IMG + y) * NSLICE) * (NSING * NECHO * 2) + n * 6;
    const float* sbase = smap + ((size_t)(c * NPIX + x * IMG + y) * NSLICE) * 2;

    float accr[NSLICE][NECHO];
    float acci[NSLICE][NECHO];
#pragma unroll
    for (int kz = 0; kz < NSLICE; ++kz)
#pragma unroll
        for (int e = 0; e < NECHO; ++e) { accr[kz][e] = 0.f; acci[kz][e] = 0.f; }

    for (int z = 0; z < NSLICE; ++z) {
        float2 sm = *(const float2*)(sbase + z * 2);
        const float* v = vbase + z * (NSING * NECHO * 2);
        float2 v0 = *(const float2*)(v + 0);
        float2 v1 = *(const float2*)(v + 2);
        float2 v2 = *(const float2*)(v + 4);

        float tr[3], ti[3];
        tr[0] = v0.x * sm.x - v0.y * sm.y;  ti[0] = v0.x * sm.y + v0.y * sm.x;
        tr[1] = v1.x * sm.x - v1.y * sm.y;  ti[1] = v1.x * sm.y + v1.y * sm.x;
        tr[2] = v2.x * sm.x - v2.y * sm.y;  ti[2] = v2.x * sm.y + v2.y * sm.x;

#pragma unroll
        for (int kz = 0; kz < NSLICE; ++kz) {
            float2 w = W[kz][z];
#pragma unroll
            for (int e = 0; e < NECHO; ++e) {
                accr[kz][e] = fmaf(tr[e], w.x, accr[kz][e]);
                accr[kz][e] = fmaf(-ti[e], w.y, accr[kz][e]);
                acci[kz][e] = fmaf(tr[e], w.y, acci[kz][e]);
                acci[kz][e] = fmaf(ti[e], w.x, acci[kz][e]);
            }
        }
    }

#pragma unroll
    for (int kz = 0; kz < NSLICE; ++kz)
#pragma unroll
        for (int e = 0; e < NECHO; ++e) {
            g_scf[((size_t)(kz * NCOIL + c) * (NSING * NECHO) + n * NECHO + e) * NPIX + pix]
                = make_float2(accr[kz][e], acci[kz][e]);
        }
}

// ---------------------------------------------------------------------------
// Stage B: mix with Ur, gather slice bin: imgW[r][e*4+c][pix]
// ---------------------------------------------------------------------------
__global__ __launch_bounds__(256)
void stageB_kernel(const float* __restrict__ ur_list,   // [1,32,4]
                   const int*   __restrict__ sbin)      // [32]
{
    const int pix = blockIdx.x * 256 + threadIdx.x;
    const int r   = blockIdx.y;
    const int kzr = sbin[r];

    float u[NSING];
#pragma unroll
    for (int n = 0; n < NSING; ++n) u[n] = ur_list[r * NSING + n];

    const float2* base = g_scf + (size_t)(kzr * NCOIL) * (NSING * NECHO) * NPIX;

#pragma unroll
    for (int e = 0; e < NECHO; ++e) {
#pragma unroll
        for (int c = 0; c < NCOIL; ++c) {
            float ar = 0.f, ai = 0.f;
#pragma unroll
            for (int n = 0; n < NSING; ++n) {
                float2 s = base[((size_t)c * (NSING * NECHO) + n * NECHO + e) * NPIX + pix];
                ar = fmaf(u[n], s.x, ar);
                ai = fmaf(u[n], s.y, ai);
            }
            g_imgW[((size_t)r * NEC + e * NCOIL + c) * NPIX + pix] = make_float2(ar, ai);
        }
    }
}

// ---------------------------------------------------------------------------
// Phase tables, parallel over 4 x-segments of 16. grid 32, block 384.
// ---------------------------------------------------------------------------
__global__ __launch_bounds__(384)
void exgen_kernel(const float* __restrict__ ktraj)   // [1,32,96,2]
{
    const int r = blockIdx.x;
    const int p = threadIdx.x % NPT;
    const int g = threadIdx.x / NPT;       // 0..3, 16 steps each
    const float w0 = ktraj[(r * NPT + p) * 2 + 0];
    const float w1 = ktraj[(r * NPT + p) * 2 + 1];

    {
        float s, c; sincosf(w0, &s, &c);                      // step exp(-i*w0)
        float pr, pi; sincosf(w0 * (32.0f - g * 16.0f), &pi, &pr);
#pragma unroll 4
        for (int j = 0; j < 16; ++j) {
            int x = g * 16 + j;
            size_t idx = ((size_t)r * IMG + x) * NPT + p;
            g_exp_[idx] = make_float2(pr, pi);
            g_exr_[idx] = make_float2(-pi, pr);
            float t = pr;
            pr = fmaf(pr, c, pi * s);
            pi = fmaf(pi, c, -(t * s));
        }
    }
    {
        float s, c; sincosf(w1, &s, &c);
        float pr, pi; sincosf(w1 * (32.0f - g * 16.0f), &pi, &pr);
#pragma unroll 4
        for (int j = 0; j < 16; ++j) {
            int y = g * 16 + j;
            g_ey_[((size_t)r * IMG + y) * NPT + p] = make_float2(pr, pi);
            float t = pr;
            pr = fmaf(pr, c, pi * s);
            pi = fmaf(pi, c, -(t * s));
        }
    }
}

// ---------------------------------------------------------------------------
// NUFFT: grid (32 r, 12 ec, 2 p-half), block 192, 4p x 4y thread tiles.
// Pre-rotated u64 phase tables in smem -> mainloop is LDS + dup + FFMA2 only.
// x processed in 2 smem phases of 32.  smem ~40.5KB -> 5 blocks/SM.
// ---------------------------------------------------------------------------
#define TS    66    // padded y-stride for transposed image
#define XPH   32    // x per smem phase
#define PBLK  48    // points per block

__global__ __launch_bounds__(192, 5)
void nufft_kernel(float2* __restrict__ out)   // [96,4,32,3] complex
{
    extern __shared__ unsigned char shraw[];
    float2* sT  = (float2*)shraw;                                // [32][TS]
    u64*    sEp = (u64*)(shraw + XPH * TS * sizeof(float2));     // [32][48]
    u64*    sEr = sEp + XPH * PBLK;                              // [32][48]
    float2* sRed = (float2*)shraw;                               // overlay on sT

    const int r   = blockIdx.x;
    const int ec  = blockIdx.y;
    const int ph  = blockIdx.z;
    const int tid = threadIdx.x;

    const int tx = tid % 12;          // p-tile
    const int ty = tid / 12;          // y-tile
    const int y0 = ty * 4;

    const float2* gimg = g_imgW + (size_t)(r * NEC + ec) * NPIX;
    const float2* gep  = g_exp_ + (size_t)r * IMG * NPT + ph * PBLK;
    const float2* ger  = g_exr_ + (size_t)r * IMG * NPT + ph * PBLK;

    u64 acc[4][4];
#pragma unroll
    for (int a = 0; a < 4; ++a)
#pragma unroll
        for (int b = 0; b < 4; ++b) acc[a][b] = 0ull;

    for (int xb = 0; xb < IMG; xb += XPH) {
        if (xb) __syncthreads();

        // image slab, transposed: sT[xl][y] = img[y][xb+xl]
        for (int i = tid; i < XPH * IMG; i += 192) {
            int xl = i & (XPH - 1), y = i >> 5;
            sT[xl * TS + y] = gimg[y * IMG + xb + xl];
        }
        // pre-rotated phase slabs (u64 == float2 bitwise)
        for (int i = tid; i < XPH * PBLK; i += 192) {
            int xl = i / PBLK, pl = i % PBLK;
            float2 vp = gep[(xb + xl) * NPT + pl];
            float2 vr = ger[(xb + xl) * NPT + pl];
            sEp[i] = pack2(vp.x, vp.y);
            sEr[i] = pack2(vr.x, vr.y);
        }
        __syncthreads();

#pragma unroll 4
        for (int xl = 0; xl < XPH; ++xl) {
            const u64* pe = sEp + xl * PBLK;
            const u64* pr = sEr + xl * PBLK;
            ulonglong2 epA = *(const ulonglong2*)(pe + 2 * tx);       // p, p+1
            ulonglong2 epB = *(const ulonglong2*)(pe + 2 * tx + 24);  // p+24, p+25
            ulonglong2 erA = *(const ulonglong2*)(pr + 2 * tx);
            ulonglong2 erB = *(const ulonglong2*)(pr + 2 * tx + 24);

            const float4* ti = (const float4*)(sT + xl * TS + y0);
            float4 i01 = ti[0], i23 = ti[1];
            float ivx[4] = { i01.x, i01.z, i23.x, i23.z };
            float ivy[4] = { i01.y, i01.w, i23.y, i23.w };

#pragma unroll
            for (int yy = 0; yy < 4; ++yy) {
                u64 dx = dup2(ivx[yy]);
                u64 dy = dup2(ivy[yy]);
                fma2(acc[0][yy], dx, epA.x); fma2(acc[0][yy], dy, erA.x);
                fma2(acc[1][yy], dx, epA.y); fma2(acc[1][yy], dy, erA.y);
                fma2(acc[2][yy], dx, epB.x); fma2(acc[2][yy], dy, erB.x);
                fma2(acc[3][yy], dx, epB.y); fma2(acc[3][yy], dy, erB.y);
            }
        }
    }

    __syncthreads();                  // mainloop done; reuse sT as sRed

    // epilogue: contract with ey, partial per ty, reduce
    const int pg[4] = { 2 * tx, 2 * tx + 1, 2 * tx + 24, 2 * tx + 25 };
    const float2* gey = g_ey_ + (size_t)r * IMG * NPT + ph * PBLK;
#pragma unroll
    for (int pp = 0; pp < 4; ++pp) {
        float orr = 0.f, oii = 0.f;
#pragma unroll
        for (int yy = 0; yy < 4; ++yy) {
            float2 t  = unpack2(acc[pp][yy]);
            float2 ey = gey[(y0 + yy) * NPT + pg[pp]];
            orr = fmaf(t.x,  ey.x, orr);
            orr = fmaf(-t.y, ey.y, orr);
            oii = fmaf(t.x,  ey.y, oii);
            oii = fmaf(t.y,  ey.x, oii);
        }
        sRed[pg[pp] * 16 + ty] = make_float2(orr, oii);
    }
    __syncthreads();

    if (tid < PBLK) {
        float sr = 0.f, si = 0.f;
#pragma unroll
        for (int q = 0; q < 16; ++q) {
            float2 v = sRed[tid * 16 + q];
            sr += v.x; si += v.y;
        }
        const int p = ph * PBLK + tid;
        const int e = ec >> 2;
        const int c = ec & 3;
        out[((p * NCOIL + c) * NRO + r) * NECHO + e] = make_float2(sr, si);
    }
}

// ---------------------------------------------------------------------------
extern "C" void kernel_launch(void* const* d_in, const int* in_sizes, int n_in,
                              void* d_out, int out_size)
{
    const float* singulars = (const float*)d_in[0];
    const float* smap      = (const float*)d_in[1];
    const float* ktraj     = (const float*)d_in[2];
    const float* ur_list   = (const float*)d_in[3];
    const int*   sbin      = (const int*)d_in[4];
    // d_in[5] = dc (unused by the forward reference)

    float2* out = (float2*)d_out;

    const int smemNufft = XPH * TS * (int)sizeof(float2)
                        + 2 * XPH * PBLK * (int)sizeof(u64);   // ~40.5KB
    cudaFuncSetAttribute(nufft_kernel, cudaFuncAttributeMaxDynamicSharedMemorySize, smemNufft);

    stageA_kernel<<<dim3(NPIX / 256, 16), 256>>>(singulars, smap);
    exgen_kernel<<<NRO, 384>>>(ktraj);
    stageB_kernel<<<dim3(NPIX / 256, NRO), 256>>>(ur_list, sbin);
    nufft_kernel<<<dim3(NRO, NEC, 2), 192, smemNufft>>>(out);
}

// round 6
// speedup vs baseline: 1.0537x; 1.0269x over previous
#include <cuda_runtime.h>
#include <math.h>

#define IMG    64
#define NSLICE 16
#define NCOIL  4
#define NSING  4
#define NECHO  3
#define NRO    32
#define NPT    96
#define NEC    (NECHO * NCOIL)   // 12
#define NPIX   (IMG * IMG)       // 4096

typedef unsigned long long u64;

// ---- packed f32x2 helpers ---------------------------------------------------
__device__ __forceinline__ u64 pack2(float lo, float hi) {
    u64 r;
    asm("mov.b64 %0, {%1, %2};" : "=l"(r)
        : "r"(__float_as_uint(lo)), "r"(__float_as_uint(hi)));
    return r;
}
__device__ __forceinline__ u64 dup2(float v) { return pack2(v, v); }
__device__ __forceinline__ void fma2(u64& d, u64 a, u64 b) {
    asm("fma.rn.f32x2 %0, %1, %2, %3;" : "=l"(d) : "l"(a), "l"(b), "l"(d));
}
__device__ __forceinline__ float2 unpack2(u64 v) {
    unsigned lo, hi;
    asm("mov.b64 {%0, %1}, %2;" : "=r"(lo), "=r"(hi) : "l"(v));
    return make_float2(__uint_as_float(lo), __uint_as_float(hi));
}

// scf[kz][c][j=n*3+e][pix]  (25 MB)
__device__ float2 g_scf[NSLICE * NCOIL * (NSING * NECHO) * NPIX];
// imgW[r][ec=e*4+c][pix]    (12.6 MB)
__device__ float2 g_imgW[NRO * NEC * NPIX];
// phase tables [r][x][p]
__device__ float2 g_exp_[NRO * IMG * NPT];   // exp(-i*w0*(x-32)) = (re, im)
__device__ float2 g_exr_[NRO * IMG * NPT];   // rotated:            (-im, re)
__device__ float2 g_ey_[NRO * IMG * NPT];    // exp(-i*w1*(y-32))

// ---------------------------------------------------------------------------
// Stage A: z-DFT (all 16 kz) of sign(z)*singulars*smap, per (pix, c, n).
// ---------------------------------------------------------------------------
__global__ __launch_bounds__(256, 2)
void stageA_kernel(const float* __restrict__ singulars,   // [64,64,16,4,3,2]
                   const float* __restrict__ smap)        // [4,64,64,16,2]
{
    const int pix = blockIdx.x * 256 + threadIdx.x;
    const int cn  = blockIdx.y;
    const int c   = cn >> 2;
    const int n   = cn & 3;
    const int x   = pix & (IMG - 1);
    const int y   = pix >> 6;

    __shared__ float2 W[NSLICE][NSLICE];
    {
        int kz = threadIdx.x >> 4, z = threadIdx.x & 15;
        float ang = -(2.0f * (float)M_PI / (float)NSLICE) * (float)(kz * z);
        float s, co; sincosf(ang, &s, &co);
        float sgn = (z & 1) ? -1.0f : 1.0f;
        W[kz][z] = make_float2(co * sgn, s * sgn);
    }
    __syncthreads();

    const float* vbase = singulars + ((size_t)(x * IMG + y) * NSLICE) * (NSING * NECHO * 2) + n * 6;
    const float* sbase = smap + ((size_t)(c * NPIX + x * IMG + y) * NSLICE) * 2;

    float accr[NSLICE][NECHO];
    float acci[NSLICE][NECHO];
#pragma unroll
    for (int kz = 0; kz < NSLICE; ++kz)
#pragma unroll
        for (int e = 0; e < NECHO; ++e) { accr[kz][e] = 0.f; acci[kz][e] = 0.f; }

    for (int z = 0; z < NSLICE; ++z) {
        float2 sm = *(const float2*)(sbase + z * 2);
        const float* v = vbase + z * (NSING * NECHO * 2);
        float2 v0 = *(const float2*)(v + 0);
        float2 v1 = *(const float2*)(v + 2);
        float2 v2 = *(const float2*)(v + 4);

        float tr[3], ti[3];
        tr[0] = v0.x * sm.x - v0.y * sm.y;  ti[0] = v0.x * sm.y + v0.y * sm.x;
        tr[1] = v1.x * sm.x - v1.y * sm.y;  ti[1] = v1.x * sm.y + v1.y * sm.x;
        tr[2] = v2.x * sm.x - v2.y * sm.y;  ti[2] = v2.x * sm.y + v2.y * sm.x;

#pragma unroll
        for (int kz = 0; kz < NSLICE; ++kz) {
            float2 w = W[kz][z];
#pragma unroll
            for (int e = 0; e < NECHO; ++e) {
                accr[kz][e] = fmaf(tr[e], w.x, accr[kz][e]);
                accr[kz][e] = fmaf(-ti[e], w.y, accr[kz][e]);
                acci[kz][e] = fmaf(tr[e], w.y, acci[kz][e]);
                acci[kz][e] = fmaf(ti[e], w.x, acci[kz][e]);
            }
        }
    }

#pragma unroll
    for (int kz = 0; kz < NSLICE; ++kz)
#pragma unroll
        for (int e = 0; e < NECHO; ++e) {
            g_scf[((size_t)(kz * NCOIL + c) * (NSING * NECHO) + n * NECHO + e) * NPIX + pix]
                = make_float2(accr[kz][e], acci[kz][e]);
        }
}

// ---------------------------------------------------------------------------
// Stage B: mix with Ur, gather slice bin: imgW[r][e*4+c][pix]
// ---------------------------------------------------------------------------
__global__ __launch_bounds__(256)
void stageB_kernel(const float* __restrict__ ur_list,   // [1,32,4]
                   const int*   __restrict__ sbin)      // [32]
{
    const int pix = blockIdx.x * 256 + threadIdx.x;
    const int r   = blockIdx.y;
    const int kzr = sbin[r];

    float u[NSING];
#pragma unroll
    for (int n = 0; n < NSING; ++n) u[n] = ur_list[r * NSING + n];

    const float2* base = g_scf + (size_t)(kzr * NCOIL) * (NSING * NECHO) * NPIX;

#pragma unroll
    for (int e = 0; e < NECHO; ++e) {
#pragma unroll
        for (int c = 0; c < NCOIL; ++c) {
            float ar = 0.f, ai = 0.f;
#pragma unroll
            for (int n = 0; n < NSING; ++n) {
                float2 s = base[((size_t)c * (NSING * NECHO) + n * NECHO + e) * NPIX + pix];
                ar = fmaf(u[n], s.x, ar);
                ai = fmaf(u[n], s.y, ai);
            }
            g_imgW[((size_t)r * NEC + e * NCOIL + c) * NPIX + pix] = make_float2(ar, ai);
        }
    }
}

// ---------------------------------------------------------------------------
// Phase tables, parallel over 4 x-segments of 16. grid 32, block 384.
// ---------------------------------------------------------------------------
__global__ __launch_bounds__(384)
void exgen_kernel(const float* __restrict__ ktraj)   // [1,32,96,2]
{
    const int r = blockIdx.x;
    const int p = threadIdx.x % NPT;
    const int g = threadIdx.x / NPT;       // 0..3, 16 steps each
    const float w0 = ktraj[(r * NPT + p) * 2 + 0];
    const float w1 = ktraj[(r * NPT + p) * 2 + 1];

    {
        float s, c; sincosf(w0, &s, &c);                      // step exp(-i*w0)
        float pr, pi; sincosf(w0 * (32.0f - g * 16.0f), &pi, &pr);
#pragma unroll 4
        for (int j = 0; j < 16; ++j) {
            int x = g * 16 + j;
            size_t idx = ((size_t)r * IMG + x) * NPT + p;
            g_exp_[idx] = make_float2(pr, pi);
            g_exr_[idx] = make_float2(-pi, pr);
            float t = pr;
            pr = fmaf(pr, c, pi * s);
            pi = fmaf(pi, c, -(t * s));
        }
    }
    {
        float s, c; sincosf(w1, &s, &c);
        float pr, pi; sincosf(w1 * (32.0f - g * 16.0f), &pi, &pr);
#pragma unroll 4
        for (int j = 0; j < 16; ++j) {
            int y = g * 16 + j;
            g_ey_[((size_t)r * IMG + y) * NPT + p] = make_float2(pr, pi);
            float t = pr;
            pr = fmaf(pr, c, pi * s);
            pi = fmaf(pi, c, -(t * s));
        }
    }
}

// ---------------------------------------------------------------------------
// NUFFT: grid (32 r, 12 ec), block 256 = 8 warps.
// Lane l owns points {l, l+32, l+64}; warp w owns ys [8w, 8w+8).
// Image in smem transposed [x][y] -> warp-uniform BROADCAST reads (1-phase).
// Phase tables lane-coalesced LDS.64; pre-rotated in global (no ALU packing).
// x-dim phased in chunks of 16 for the tables; image resident whole.
// smem 63KB -> 3 blocks/SM -> single wave (444 >= 384).
// ---------------------------------------------------------------------------
#define TS    66    // padded y-stride (float2) for transposed image (16B-aligned rows)
#define XPH   16    // x per table phase

__global__ __launch_bounds__(256, 3)
void nufft_kernel(float2* __restrict__ out)   // [96,4,32,3] complex
{
    extern __shared__ unsigned char shraw[];
    float2* sT   = (float2*)shraw;                                  // [64][TS]
    u64*    sEp  = (u64*)(shraw + IMG * TS * sizeof(float2));       // [16][96]
    u64*    sEr  = sEp + XPH * NPT;                                 // [16][96]
    float2* sRed = (float2*)(sEr + XPH * NPT);                      // [96][8]

    const int r    = blockIdx.x;
    const int ec   = blockIdx.y;
    const int tid  = threadIdx.x;
    const int lane = tid & 31;
    const int w    = tid >> 5;
    const int y0   = w * 8;

    const float2* gimg = g_imgW + (size_t)(r * NEC + ec) * NPIX;
    const u64* gep = (const u64*)(g_exp_ + (size_t)r * IMG * NPT);
    const u64* ger = (const u64*)(g_exr_ + (size_t)r * IMG * NPT);

    // load image, transposed: sT[x][y] = img[y][x]
    for (int i = tid; i < NPIX; i += 256) {
        int x = i & 63, y = i >> 6;
        sT[x * TS + y] = gimg[i];
    }

    u64 acc[3][8];
#pragma unroll
    for (int a = 0; a < 3; ++a)
#pragma unroll
        for (int b = 0; b < 8; ++b) acc[a][b] = 0ull;

    for (int xb = 0; xb < IMG; xb += XPH) {
        if (xb) __syncthreads();
        // table slab for xs [xb, xb+16): contiguous copy
        for (int i = tid; i < XPH * NPT; i += 256) {
            sEp[i] = gep[xb * NPT + i];
            sEr[i] = ger[xb * NPT + i];
        }
        __syncthreads();

#pragma unroll 2
        for (int xl = 0; xl < XPH; ++xl) {
            const u64* pe = sEp + xl * NPT;
            const u64* pr = sEr + xl * NPT;
            u64 ep0 = pe[lane], ep1 = pe[lane + 32], ep2 = pe[lane + 64];
            u64 er0 = pr[lane], er1 = pr[lane + 32], er2 = pr[lane + 64];

            // warp-uniform broadcast: 8 ys = 4x LDS.128
            const float4* ti = (const float4*)(sT + (xb + xl) * TS + y0);
            float4 iA = ti[0], iB = ti[1], iC = ti[2], iD = ti[3];
            float ivx[8] = { iA.x, iA.z, iB.x, iB.z, iC.x, iC.z, iD.x, iD.z };
            float ivy[8] = { iA.y, iA.w, iB.y, iB.w, iC.y, iC.w, iD.y, iD.w };

#pragma unroll
            for (int yy = 0; yy < 8; ++yy) {
                u64 dx = dup2(ivx[yy]);
                u64 dy = dup2(ivy[yy]);
                fma2(acc[0][yy], dx, ep0); fma2(acc[0][yy], dy, er0);
                fma2(acc[1][yy], dx, ep1); fma2(acc[1][yy], dy, er1);
                fma2(acc[2][yy], dx, ep2); fma2(acc[2][yy], dy, er2);
            }
        }
    }

    // epilogue: contract with ey over this warp's 8 ys
    const float2* gey = g_ey_ + (size_t)r * IMG * NPT;
#pragma unroll
    for (int k = 0; k < 3; ++k) {
        const int p = lane + 32 * k;
        float orr = 0.f, oii = 0.f;
#pragma unroll
        for (int yy = 0; yy < 8; ++yy) {
            float2 t  = unpack2(acc[k][yy]);
            float2 ey = gey[(y0 + yy) * NPT + p];
            orr = fmaf(t.x,  ey.x, orr);
            orr = fmaf(-t.y, ey.y, orr);
            oii = fmaf(t.x,  ey.y, oii);
            oii = fmaf(t.y,  ey.x, oii);
        }
        sRed[p * 8 + w] = make_float2(orr, oii);
    }
    __syncthreads();

    if (tid < NPT) {
        float sr = 0.f, si = 0.f;
#pragma unroll
        for (int q = 0; q < 8; ++q) {
            float2 v = sRed[tid * 8 + q];
            sr += v.x; si += v.y;
        }
        const int e = ec >> 2;
        const int c = ec & 3;
        out[((tid * NCOIL + c) * NRO + r) * NECHO + e] = make_float2(sr, si);
    }
}

// ---------------------------------------------------------------------------
extern "C" void kernel_launch(void* const* d_in, const int* in_sizes, int n_in,
                              void* d_out, int out_size)
{
    const float* singulars = (const float*)d_in[0];
    const float* smap      = (const float*)d_in[1];
    const float* ktraj     = (const float*)d_in[2];
    const float* ur_list   = (const float*)d_in[3];
    const int*   sbin      = (const int*)d_in[4];
    // d_in[5] = dc (unused by the forward reference)

    float2* out = (float2*)d_out;

    const int smemNufft = IMG * TS * (int)sizeof(float2)        // sT     33792
                        + 2 * XPH * NPT * (int)sizeof(u64)      // tables 24576
                        + NPT * 8 * (int)sizeof(float2);        // sRed    6144
    cudaFuncSetAttribute(nufft_kernel, cudaFuncAttributeMaxDynamicSharedMemorySize, smemNufft);

    stageA_kernel<<<dim3(NPIX / 256, 16), 256>>>(singulars, smap);
    exgen_kernel<<<NRO, 384>>>(ktraj);
    stageB_kernel<<<dim3(NPIX / 256, NRO), 256>>>(ur_list, sbin);
    nufft_kernel<<<dim3(NRO, NEC), 256, smemNufft>>>(out);
}